// round 10
// baseline (speedup 1.0000x reference)
#include <cuda_runtime.h>
#include <cuda_bf16.h>
#include <math.h>
#include <float.h>
#include <stdint.h>

// Gate_33827162423867 — fused HMMA router, concurrency-scaled.
// grid=256 CTAs x 64 tokens (2 CTAs/SM where possible) to scale per-SM
// memory-level parallelism past the ~5.6GB/s per-CTA delivery cap observed
// at grid=128. bf16 2-split (hi/lo, 3 products, fp32 accum, mma.sync) ->
// FTZ softmax -> top-8 of probs; knife-edge tokens recomputed exactly
// in-CTA (serial fp32 FMA per 1024-slice, split-K4 fold == cublas order).
// Output: d_out float*, [0,T*8) gate weights, [T*8, 2*T*8) indices-as-float.

#define NE    64
#define TB    64
#define KCH   64
#define NT    256
#define TOPK  8

#define EPS_GAP 0.01f
#define EPS_B   0.01f
#define LN_FLT_MIN -87.33654475055310898657124730373f

#define RS    72      // bf16 tile row stride (elements); 144B rows
#define SSTR  65      // scores row stride (floats)
#define FSTR  73      // fixup row stride (floats)
#define MAXFLAG 32

// raw x staging: 64 rows x 72-float (288B) rows
#define XSTRF 72
#define XRAW_BYTES (TB * XSTRF * 4)      // 18432
#define NSTAGE 2
#define RAW_TOTAL (NSTAGE * XRAW_BYTES)  // 36864

// bf16 tiles (single buffer): 64 x RS bf16 = 9216 B each
#define SM_XH (RAW_TOTAL + 0)
#define SM_XL (RAW_TOTAL + 9216)
#define SM_WH (RAW_TOTAL + 18432)
#define SM_WL (RAW_TOTAL + 27648)
#define SMEM_DYN (RAW_TOTAL + 36864)     // 73728

#define SM_FIX XRAW_BYTES  // fixup rows alias raw stage 1 (GEMM done by then)

// ---------------- helpers ----------------
__device__ __forceinline__ uint32_t smem_u32(const void* p) {
    uint32_t a;
    asm("{ .reg .u64 t; cvta.to.shared.u64 t, %1; cvt.u32.u64 %0, t; }"
        : "=r"(a) : "l"(p));
    return a;
}
__device__ __forceinline__ uint32_t cvt_bf16x2(float lo, float hi) {
    uint32_t r;
    asm("cvt.rn.bf16x2.f32 %0, %1, %2;" : "=r"(r) : "f"(hi), "f"(lo));
    return r;
}
__device__ __forceinline__ float bflo_f(uint32_t h) { return __uint_as_float(h << 16); }
__device__ __forceinline__ float bfhi_f(uint32_t h) { return __uint_as_float(h & 0xFFFF0000u); }

__device__ __forceinline__ void cp16(uint32_t smem_addr, const void* gptr) {
    asm volatile("cp.async.cg.shared.global [%0], [%1], 16;"
                 :: "r"(smem_addr), "l"(gptr));
}
__device__ __forceinline__ void cp_commit() {
    asm volatile("cp.async.commit_group;" ::: "memory");
}
__device__ __forceinline__ void cp_wait1() {
    asm volatile("cp.async.wait_group 1;" ::: "memory");
}

__device__ __forceinline__ void ldm_x4(uint32_t addr, uint32_t& r0, uint32_t& r1,
                                       uint32_t& r2, uint32_t& r3) {
    asm volatile("ldmatrix.sync.aligned.m8n8.x4.shared.b16 {%0,%1,%2,%3}, [%4];"
                 : "=r"(r0), "=r"(r1), "=r"(r2), "=r"(r3) : "r"(addr));
}
__device__ __forceinline__ void mma_bf16(float* d, uint32_t a0, uint32_t a1,
                                         uint32_t a2, uint32_t a3,
                                         uint32_t b0, uint32_t b1) {
    asm volatile(
        "mma.sync.aligned.m16n8k16.row.col.f32.bf16.bf16.f32 "
        "{%0,%1,%2,%3}, {%4,%5,%6,%7}, {%8,%9}, {%0,%1,%2,%3};"
        : "+f"(d[0]), "+f"(d[1]), "+f"(d[2]), "+f"(d[3])
        : "r"(a0), "r"(a1), "r"(a2), "r"(a3), "r"(b0), "r"(b1));
}

// ================= single fused kernel =================
__global__ __launch_bounds__(NT, 2)
void gate_kernel(const float* __restrict__ x,
                 const float* __restrict__ w,
                 float* __restrict__ out,
                 int dim, int tokens)
{
    extern __shared__ char dyn[];
    __shared__ int   s_nflag;
    __shared__ int   s_flags[MAXFLAG];
    __shared__ float s_part[2][4 * NE];

    const uint32_t sbase = smem_u32(dyn);
    const int tid  = threadIdx.x;
    const int wid  = tid >> 5;
    const int lane = tid & 31;
    const int token0 = blockIdx.x * TB;

    if (tid == 0) s_nflag = 0;

    const int nchunks = dim / KCH;        // 64

    // cp.async: x only; 1024 16B ops -> 4/thread
    auto issue_x = [&](int c) {
        const uint32_t so = (uint32_t)((c & 1) * XRAW_BYTES);
        const int k0 = c * KCH;
        #pragma unroll
        for (int i = 0; i < 4; i++) {
            int o   = tid + i * NT;            // 0..1023
            int row = o >> 4;
            int seg = o & 15;
            uint32_t dst = sbase + so + (uint32_t)(row * (XSTRF * 4) + seg * 16);
            const float* src = x + (size_t)(token0 + row) * dim + k0 + seg * 4;
            cp16(dst, src);
        }
    };

    // w register preload (L2-resident stream)
    const int wrow = tid >> 2;            // 0..63
    const int wc0  = (tid & 3) * 4;       // 0,4,8,12
    float4 wr[4];
    auto load_w = [&](int c) {
        const float* wsrc = w + (size_t)wrow * dim + c * KCH;
        #pragma unroll
        for (int j = 0; j < 4; j++)
            wr[j] = *reinterpret_cast<const float4*>(wsrc + wc0 + j * 16);
    };

    issue_x(0); cp_commit();
    issue_x(1); cp_commit();
    load_w(0);

    // convert mapping for x
    const int xrow = tid >> 2;            // 0..63
    const int xc0  = (tid & 3) * 4;

    // MMA mapping: warp = 16 tokens x 32 experts
    const int tg   = wid & 3;             // token group
    const int eh   = wid >> 2;            // expert half
    const int tokb = tg * 16;
    const uint32_t aoff = (uint32_t)((tokb + (lane & 7) + (((lane >> 3) & 1) * 8)) * (RS * 2)
                                     + ((lane >> 4) * 16));
    const uint32_t boff_base = (uint32_t)(((lane & 7) + ((lane >> 4) * 8)) * (RS * 2)
                                          + (((lane >> 3) & 1) * 16));

    float acc[4][4];
    #pragma unroll
    for (int n = 0; n < 4; n++)
        #pragma unroll
        for (int i = 0; i < 4; i++) acc[n][i] = 0.0f;

    for (int c = 0; c < nchunks; c++) {
        const uint32_t so = (uint32_t)((c & 1) * XRAW_BYTES);

        cp_wait1();            // x chunk c landed
        __syncthreads();       // visible to all; prev MMA done (bf16 free)

        // ---- convert: x from smem raw, w from registers ----
        {
            const float* xraw = reinterpret_cast<const float*>(dyn + so);
            char* xh = dyn + SM_XH;
            char* xl = dyn + SM_XL;
            #pragma unroll
            for (int j = 0; j < 4; j++) {
                const int col = xc0 + j * 16;
                float4 a = *reinterpret_cast<const float4*>(xraw + xrow * XSTRF + col);
                uint32_t h0 = cvt_bf16x2(a.x, a.y);
                uint32_t h1 = cvt_bf16x2(a.z, a.w);
                uint32_t l0 = cvt_bf16x2(a.x - bflo_f(h0), a.y - bfhi_f(h0));
                uint32_t l1 = cvt_bf16x2(a.z - bflo_f(h1), a.w - bfhi_f(h1));
                uint32_t off = (uint32_t)(xrow * (RS * 2) + col * 2);
                *reinterpret_cast<uint2*>(xh + off) = make_uint2(h0, h1);
                *reinterpret_cast<uint2*>(xl + off) = make_uint2(l0, l1);
            }
            char* wh = dyn + SM_WH;
            char* wl = dyn + SM_WL;
            #pragma unroll
            for (int j = 0; j < 4; j++) {
                const int col = wc0 + j * 16;
                float4 a = wr[j];
                uint32_t h0 = cvt_bf16x2(a.x, a.y);
                uint32_t h1 = cvt_bf16x2(a.z, a.w);
                uint32_t l0 = cvt_bf16x2(a.x - bflo_f(h0), a.y - bfhi_f(h0));
                uint32_t l1 = cvt_bf16x2(a.z - bflo_f(h1), a.w - bfhi_f(h1));
                uint32_t off = (uint32_t)(wrow * (RS * 2) + col * 2);
                *reinterpret_cast<uint2*>(wh + off) = make_uint2(h0, h1);
                *reinterpret_cast<uint2*>(wl + off) = make_uint2(l0, l1);
            }
        }
        __syncthreads();       // bf16 ready; raw stage (c&1) free

        if (c + 2 < nchunks) issue_x(c + 2);
        cp_commit();
        if (c + 1 < nchunks) load_w(c + 1);

        // ---- MMA: 4 k-steps x 2 expert-pairs x 3 products ----
        #pragma unroll
        for (int ks = 0; ks < 4; ks++) {
            const uint32_t kb = (uint32_t)(ks * 32);
            uint32_t ah0, ah1, ah2, ah3, al0, al1, al2, al3;
            ldm_x4(sbase + SM_XH + aoff + kb, ah0, ah1, ah2, ah3);
            ldm_x4(sbase + SM_XL + aoff + kb, al0, al1, al2, al3);
            #pragma unroll
            for (int q = 0; q < 2; q++) {
                const int p = 2 * eh + q;
                const uint32_t bo = boff_base + (uint32_t)(p * 16 * (RS * 2)) + kb;
                uint32_t bh0, bh1, bh2, bh3, bl0, bl1, bl2, bl3;
                ldm_x4(sbase + SM_WH + bo, bh0, bh1, bh2, bh3);
                ldm_x4(sbase + SM_WL + bo, bl0, bl1, bl2, bl3);
                mma_bf16(acc[2 * q], ah0, ah1, ah2, ah3, bh0, bh1);
                mma_bf16(acc[2 * q], ah0, ah1, ah2, ah3, bl0, bl1);
                mma_bf16(acc[2 * q], al0, al1, al2, al3, bh0, bh1);
                mma_bf16(acc[2 * q + 1], ah0, ah1, ah2, ah3, bh2, bh3);
                mma_bf16(acc[2 * q + 1], ah0, ah1, ah2, ah3, bl2, bl3);
                mma_bf16(acc[2 * q + 1], al0, al1, al2, al3, bh2, bh3);
            }
        }
    }

    __syncthreads();

    // ---- accumulators -> padded smem scores [64][SSTR] (aliases raw) ----
    float* scores = reinterpret_cast<float*>(dyn);
    {
        const int g  = lane >> 2;
        const int t2 = (lane & 3) * 2;
        #pragma unroll
        for (int n = 0; n < 4; n++) {
            const int col = eh * 32 + n * 8 + t2;
            scores[(tokb + g) * SSTR + col]         = acc[n][0];
            scores[(tokb + g) * SSTR + col + 1]     = acc[n][1];
            scores[(tokb + g + 8) * SSTR + col]     = acc[n][2];
            scores[(tokb + g + 8) * SSTR + col + 1] = acc[n][3];
        }
    }
    __syncthreads();

    // ---- fast epilogue: 1 thread per token ----
    if (tid < TB) {
        float* srow = scores + tid * SSTR;
        float m = -FLT_MAX;
        #pragma unroll
        for (int e = 0; e < NE; e++) m = fmaxf(m, srow[e]);

        float denom = 0.0f;
        #pragma unroll
        for (int e = 0; e < NE; e++) {
            float q = __expf(srow[e] - m);
            if (q < FLT_MIN) q = 0.0f;
            denom += q;
        }

        bool flag = false;
        float b2 = LN_FLT_MIN + __logf(denom);
        #pragma unroll
        for (int e = 0; e < NE; e++) {
            float d = srow[e] - m;
            if (fabsf(d - LN_FLT_MIN) < EPS_B || fabsf(d - b2) < EPS_B) flag = true;
        }
        {
            unsigned long long used = 0ull;
            float prevv = 0.0f;
            for (int j = 0; j < 9; j++) {
                float best = -FLT_MAX; int bi = 0;
                for (int e = 0; e < NE; e++)
                    if (!((used >> e) & 1ull) && srow[e] > best) { best = srow[e]; bi = e; }
                used |= 1ull << bi;
                if (j > 0 && (prevv - best) < EPS_GAP) flag = true;
                prevv = best;
            }
        }

        float inv = 1.0f / denom;
        #pragma unroll
        for (int e = 0; e < NE; e++) {
            float q = __expf(srow[e] - m);
            if (q < FLT_MIN) q = 0.0f;
            q *= inv;
            if (q < FLT_MIN) q = 0.0f;
            srow[e] = q;
        }

        const int tglob = token0 + tid;
        float* out_w   = out + (size_t)tglob * TOPK;
        float* out_idx = out + (size_t)tokens * TOPK + (size_t)tglob * TOPK;
        #pragma unroll
        for (int j = 0; j < TOPK; j++) {
            float best = -1.0f; int bi = 0;
            for (int e = 0; e < NE; e++)
                if (srow[e] > best) { best = srow[e]; bi = e; }
            srow[bi] = -1.0f;
            out_w[j]   = best;
            out_idx[j] = (float)bi;
        }

        if (flag) {
            int i = atomicAdd(&s_nflag, 1);
            if (i < MAXFLAG) s_flags[i] = tid;
        }
    }
    __syncthreads();

    // ---- in-CTA exact fixup (serial fp32, split-K4 fold) ----
    const int nf = (s_nflag < MAXFLAG) ? s_nflag : MAXFLAG;
    if (nf > 0) {
        const int e  = tid & 63;
        const int sl = tid >> 6;            // slice 0..3
        const int slice = dim >> 2;         // 1024
        float* fixb = reinterpret_cast<float*>(dyn + SM_FIX);

        for (int f0 = 0; f0 < nf; f0 += 2) {
            const int f1 = (f0 + 1 < nf) ? f0 + 1 : f0;
            const float* xr0 = x + (size_t)(token0 + s_flags[f0]) * dim + sl * slice;
            const float* xr1 = x + (size_t)(token0 + s_flags[f1]) * dim + sl * slice;
            const float* wrp = w + (size_t)e * dim + sl * slice;
            float a0 = 0.0f, a1 = 0.0f;
            for (int k = 0; k < slice; k += 4) {
                float4 wv = *reinterpret_cast<const float4*>(wrp + k);
                float4 v0 = *reinterpret_cast<const float4*>(xr0 + k);
                float4 v1 = *reinterpret_cast<const float4*>(xr1 + k);
                a0 = fmaf(v0.x, wv.x, a0); a1 = fmaf(v1.x, wv.x, a1);
                a0 = fmaf(v0.y, wv.y, a0); a1 = fmaf(v1.y, wv.y, a1);
                a0 = fmaf(v0.z, wv.z, a0); a1 = fmaf(v1.z, wv.z, a1);
                a0 = fmaf(v0.w, wv.w, a0); a1 = fmaf(v1.w, wv.w, a1);
            }
            s_part[0][e * 4 + sl] = a0;
            s_part[1][e * 4 + sl] = a1;
            __syncthreads();
            if (tid < NE) {
                float t0 = ((s_part[0][tid * 4] + s_part[0][tid * 4 + 1])
                            + s_part[0][tid * 4 + 2]) + s_part[0][tid * 4 + 3];
                float t1 = ((s_part[1][tid * 4] + s_part[1][tid * 4 + 1])
                            + s_part[1][tid * 4 + 2]) + s_part[1][tid * 4 + 3];
                fixb[f0 * FSTR + tid] = t0;
                fixb[f1 * FSTR + tid] = t1;
            }
            __syncthreads();
        }

        if (tid < nf) {
            float* srow = fixb + tid * FSTR;
            float m = -FLT_MAX;
            for (int ee = 0; ee < NE; ee++) m = fmaxf(m, srow[ee]);
            float denom = 0.0f;
            for (int ee = 0; ee < NE; ee++) {
                float q = expf(srow[ee] - m);
                if (q < FLT_MIN) q = 0.0f;
                srow[ee] = q;
                denom += q;
            }
            float inv = 1.0f / denom;
            for (int ee = 0; ee < NE; ee++) {
                float q = srow[ee] * inv;
                if (q < FLT_MIN) q = 0.0f;
                srow[ee] = q;
            }
            const int tglob = token0 + s_flags[tid];
            float* out_w   = out + (size_t)tglob * TOPK;
            float* out_idx = out + (size_t)tokens * TOPK + (size_t)tglob * TOPK;
            for (int j = 0; j < TOPK; j++) {
                float best = -1.0f; int bi = 0;
                for (int ee = 0; ee < NE; ee++)
                    if (srow[ee] > best) { best = srow[ee]; bi = ee; }
                srow[bi] = -1.0f;
                out_w[j]   = best;
                out_idx[j] = (float)bi;
            }
        }
    }
}

// ================= launch =================
extern "C" void kernel_launch(void* const* d_in, const int* in_sizes, int n_in,
                              void* d_out, int out_size)
{
    const float* x = (const float*)d_in[0];
    const float* w = (const float*)d_in[1];
    // d_in[2] = bias: dead code in the reference

    const int num_experts = in_sizes[2];                 // 64
    const int dim         = in_sizes[1] / num_experts;   // 4096
    const int tokens      = in_sizes[0] / dim;           // 16384
    float* out = (float*)d_out;

    // idempotent, called every time (no static guards allowed)
    cudaFuncSetAttribute(gate_kernel,
                         cudaFuncAttributeMaxDynamicSharedMemorySize, SMEM_DYN);

    gate_kernel<<<tokens / TB, NT, SMEM_DYN>>>(x, w, out, dim, tokens);
}

// round 12
// speedup vs baseline: 1.0727x; 1.0727x over previous
#include <cuda_runtime.h>
#include <cuda_bf16.h>
#include <math.h>
#include <float.h>
#include <stdint.h>

// Gate_33827162423867 — fused HMMA router, bulk-async (TMA-engine) edition.
// All gmem->smem traffic via cp.async.bulk + mbarrier (near-zero LSU cost for
// the global leg). w is pre-converted to bf16 hi/lo, pre-swizzled chunk tiles
// by a prep kernel. bf16 2-split (3 products, fp32 accum) -> FTZ softmax ->
// top-8; knife-edge tokens recomputed exactly in-CTA (split-K4 fold).
// RACE FIX vs R11: stage refill happens at the TOP of the iteration (after
// the barrier that retires chunk c-1's MMA), refilling stage (c+2)%3 — never
// a stage whose w tile is still being read.
// Output: d_out float*, [0,T*8) gate weights, [T*8, 2*T*8) indices-as-float.

#define NE    64
#define TB    128
#define KCH   64
#define NT    256
#define TOPK  8

#define EPS_GAP 0.01f
#define EPS_B   0.01f
#define LN_FLT_MIN -87.33654475055310898657124730373f

#define RS    72       // bf16 x-tile row stride (elements); 144B rows
#define SSTR  65
#define FSTR  73
#define MAXFLAG 32

// smem layout (bytes)
#define XSTRB 272                       // raw x row stride (256B data + 16B stagger)
#define XRS   (TB * XSTRB)              // 34816 per stage
#define XR(s) ((s) * XRS)
#define WR(s) (3 * XRS + (s) * 16384)   // wh 8KB + wl 8KB per stage
#define SM_XH (3 * XRS + 3 * 16384)     // 153600
#define SM_XL (SM_XH + 18432)           // 172032
#define SMEM_DYN (SM_XL + 18432)        // 190464
#define EXPECT_BYTES 49152
#define SM_FIX 65536                    // fixup rows (aliases raw ring post-GEMM)

// pre-converted w tiles: 64 chunks x (8KB hi + 8KB lo), swizzled 128B rows
__device__ __align__(16) unsigned char g_wtiles[64 * 16384];

// ---------------- helpers ----------------
__device__ __forceinline__ uint32_t smem_u32(const void* p) {
    uint32_t a;
    asm("{ .reg .u64 t; cvta.to.shared.u64 t, %1; cvt.u32.u64 %0, t; }"
        : "=r"(a) : "l"(p));
    return a;
}
__device__ __forceinline__ uint32_t swz128(uint32_t b) {
    return b ^ ((b >> 3) & 0x70);
}
__device__ __forceinline__ uint32_t cvt_bf16x2(float lo, float hi) {
    uint32_t r;
    asm("cvt.rn.bf16x2.f32 %0, %1, %2;" : "=r"(r) : "f"(hi), "f"(lo));
    return r;
}
__device__ __forceinline__ float bflo_f(uint32_t h) { return __uint_as_float(h << 16); }
__device__ __forceinline__ float bfhi_f(uint32_t h) { return __uint_as_float(h & 0xFFFF0000u); }

__device__ __forceinline__ void mbar_init(uint32_t a, uint32_t cnt) {
    asm volatile("mbarrier.init.shared.b64 [%0], %1;" :: "r"(a), "r"(cnt) : "memory");
}
__device__ __forceinline__ void mbar_expect(uint32_t a, uint32_t bytes) {
    asm volatile("mbarrier.arrive.expect_tx.shared.b64 _, [%0], %1;"
                 :: "r"(a), "r"(bytes) : "memory");
}
__device__ __forceinline__ void mbar_wait(uint32_t a, uint32_t parity) {
    asm volatile(
        "{\n\t.reg .pred P1;\n\t"
        "WAIT_%=:\n\t"
        "mbarrier.try_wait.parity.acquire.cta.shared::cta.b64 P1, [%0], %1, 0x989680;\n\t"
        "@P1 bra.uni DONE_%=;\n\t"
        "bra.uni WAIT_%=;\n\t"
        "DONE_%=:\n\t}"
        :: "r"(a), "r"(parity) : "memory");
}
__device__ __forceinline__ void bulk_g2s(uint32_t dst, const void* src,
                                         uint32_t bytes, uint32_t mbar) {
    asm volatile(
        "cp.async.bulk.shared::cta.global.mbarrier::complete_tx::bytes "
        "[%0], [%1], %2, [%3];"
        :: "r"(dst), "l"(src), "r"(bytes), "r"(mbar) : "memory");
}
__device__ __forceinline__ void ldm_x4(uint32_t addr, uint32_t& r0, uint32_t& r1,
                                       uint32_t& r2, uint32_t& r3) {
    asm volatile("ldmatrix.sync.aligned.m8n8.x4.shared.b16 {%0,%1,%2,%3}, [%4];"
                 : "=r"(r0), "=r"(r1), "=r"(r2), "=r"(r3) : "r"(addr));
}
__device__ __forceinline__ void mma_bf16(float* d, uint32_t a0, uint32_t a1,
                                         uint32_t a2, uint32_t a3,
                                         uint32_t b0, uint32_t b1) {
    asm volatile(
        "mma.sync.aligned.m16n8k16.row.col.f32.bf16.bf16.f32 "
        "{%0,%1,%2,%3}, {%4,%5,%6,%7}, {%8,%9}, {%0,%1,%2,%3};"
        : "+f"(d[0]), "+f"(d[1]), "+f"(d[2]), "+f"(d[3])
        : "r"(a0), "r"(a1), "r"(a2), "r"(a3), "r"(b0), "r"(b1));
}

// ================= prep kernel: w -> swizzled bf16 hi/lo tiles =================
__global__ __launch_bounds__(256)
void prep_w_kernel(const float* __restrict__ w, int dim)
{
    // task: chunk c (64) x expert e (64) x 16B-block kb (8)
    int task = blockIdx.x * 256 + threadIdx.x;       // 0..32767
    int kb = task & 7;
    int e  = (task >> 3) & 63;
    int c  = task >> 9;
    const float* src = w + (size_t)e * dim + c * KCH + kb * 8;
    float v[8];
    #pragma unroll
    for (int i = 0; i < 8; i++) v[i] = src[i];
    uint32_t h[4], l[4];
    #pragma unroll
    for (int i = 0; i < 4; i++) {
        h[i] = cvt_bf16x2(v[2 * i], v[2 * i + 1]);
        l[i] = cvt_bf16x2(v[2 * i] - bflo_f(h[i]), v[2 * i + 1] - bfhi_f(h[i]));
    }
    uint32_t off = swz128((uint32_t)(e * 128 + kb * 16));
    unsigned char* base = g_wtiles + (size_t)c * 16384;
    *reinterpret_cast<uint4*>(base + off)        = make_uint4(h[0], h[1], h[2], h[3]);
    *reinterpret_cast<uint4*>(base + 8192 + off) = make_uint4(l[0], l[1], l[2], l[3]);
}

// ================= main fused kernel =================
__global__ __launch_bounds__(NT, 1)
void gate_kernel(const float* __restrict__ x,
                 const float* __restrict__ w,
                 float* __restrict__ out,
                 int dim, int tokens)
{
    extern __shared__ char dyn[];
    __shared__ __align__(8) uint64_t s_mbar[3];
    __shared__ int   s_nflag;
    __shared__ int   s_flags[MAXFLAG];
    __shared__ float s_part[2][4 * NE];

    const uint32_t sbase = smem_u32(dyn);
    const int tid  = threadIdx.x;
    const int wid  = tid >> 5;
    const int lane = tid & 31;
    const int token0 = blockIdx.x * TB;
    const int nchunks = dim / KCH;       // 64

    if (tid == 0) {
        s_nflag = 0;
        #pragma unroll
        for (int s = 0; s < 3; s++) mbar_init(smem_u32(&s_mbar[s]), 1);
        asm volatile("fence.proxy.async.shared::cta;" ::: "memory");
    }
    __syncthreads();

    uint32_t mb[3] = { smem_u32(&s_mbar[0]), smem_u32(&s_mbar[1]), smem_u32(&s_mbar[2]) };

    // issue stage s <- chunk c2
    auto issue = [&](int s, int c2) {
        if (tid < TB) {
            bulk_g2s(sbase + XR(s) + tid * XSTRB,
                     x + (size_t)(token0 + tid) * dim + c2 * KCH, 256, mb[s]);
        } else if (tid == TB) {
            bulk_g2s(sbase + WR(s), g_wtiles + (size_t)c2 * 16384, 16384, mb[s]);
        } else if (tid == TB + 1) {
            mbar_expect(mb[s], EXPECT_BYTES);
        }
    };

    // prologue: two stages in flight (stage 2 filled inside iter 0)
    issue(0, 0); issue(1, 1);

    // convert mapping: thread -> raw row (t&127), col half (t>>7)
    const int crow  = tid & 127;
    const int chalf = tid >> 7;          // 0/1 -> 32 floats each

    // MMA lane constants
    const int tokb = wid * 16;
    const uint32_t aoff = (uint32_t)((tokb + (lane & 7) + (((lane >> 3) & 1) * 8)) * (RS * 2)
                                     + ((lane >> 4) * 16));
    const int e_local = (lane & 7) + ((lane >> 4) << 3);
    const int colb    = ((lane >> 3) & 1) * 16;

    float acc[8][4];
    #pragma unroll
    for (int n = 0; n < 8; n++)
        #pragma unroll
        for (int i = 0; i < 4; i++) acc[n][i] = 0.0f;

    int ph[3] = {0, 0, 0};

    for (int c = 0; c < nchunks; c++) {
        const int s = c % 3;
        mbar_wait(mb[s], ph[s]); ph[s] ^= 1;
        __syncthreads();   // ALL warps done with chunk c-1 MMA (stage (c+2)%3 dead)

        // refill the dead stage with chunk c+2 (its x consumed at iter c-1,
        // its w reads retired by the barrier above)
        if (c + 2 < nchunks) issue((c + 2) % 3, c + 2);

        // ---- convert raw x (smem) -> bf16 hi/lo tiles ----
        {
            const char* raw = dyn + XR(s) + crow * XSTRB + chalf * 128;
            char* xh = dyn + SM_XH + crow * (RS * 2) + chalf * 64;
            char* xl = dyn + SM_XL + crow * (RS * 2) + chalf * 64;
            #pragma unroll
            for (int jj = 0; jj < 4; jj++) {       // 8 floats per iter
                float4 a = *reinterpret_cast<const float4*>(raw + jj * 32);
                float4 b = *reinterpret_cast<const float4*>(raw + jj * 32 + 16);
                uint32_t h0 = cvt_bf16x2(a.x, a.y);
                uint32_t h1 = cvt_bf16x2(a.z, a.w);
                uint32_t h2 = cvt_bf16x2(b.x, b.y);
                uint32_t h3 = cvt_bf16x2(b.z, b.w);
                uint32_t l0 = cvt_bf16x2(a.x - bflo_f(h0), a.y - bfhi_f(h0));
                uint32_t l1 = cvt_bf16x2(a.z - bflo_f(h1), a.w - bfhi_f(h1));
                uint32_t l2 = cvt_bf16x2(b.x - bflo_f(h2), b.y - bfhi_f(h2));
                uint32_t l3 = cvt_bf16x2(b.z - bflo_f(h3), b.w - bfhi_f(h3));
                *reinterpret_cast<uint4*>(xh + jj * 16) = make_uint4(h0, h1, h2, h3);
                *reinterpret_cast<uint4*>(xl + jj * 16) = make_uint4(l0, l1, l2, l3);
            }
        }
        __syncthreads();                 // bf16 x tiles ready

        // ---- MMA: 4 k-steps x 4 expert-pairs x 3 products ----
        const uint32_t wbase = sbase + WR(s);
        #pragma unroll
        for (int ks = 0; ks < 4; ks++) {
            const uint32_t kb = (uint32_t)(ks * 32);
            uint32_t ah0, ah1, ah2, ah3, al0, al1, al2, al3;
            ldm_x4(sbase + SM_XH + aoff + kb, ah0, ah1, ah2, ah3);
            ldm_x4(sbase + SM_XL + aoff + kb, al0, al1, al2, al3);
            #pragma unroll
            for (int p = 0; p < 4; p++) {
                uint32_t off = swz128((uint32_t)((p * 16 + e_local) * 128) + kb + (uint32_t)colb);
                uint32_t bh0, bh1, bh2, bh3, bl0, bl1, bl2, bl3;
                ldm_x4(wbase + off, bh0, bh1, bh2, bh3);
                ldm_x4(wbase + 8192 + off, bl0, bl1, bl2, bl3);
                mma_bf16(acc[2 * p], ah0, ah1, ah2, ah3, bh0, bh1);
                mma_bf16(acc[2 * p], ah0, ah1, ah2, ah3, bl0, bl1);
                mma_bf16(acc[2 * p], al0, al1, al2, al3, bh0, bh1);
                mma_bf16(acc[2 * p + 1], ah0, ah1, ah2, ah3, bh2, bh3);
                mma_bf16(acc[2 * p + 1], ah0, ah1, ah2, ah3, bl2, bl3);
                mma_bf16(acc[2 * p + 1], al0, al1, al2, al3, bh2, bh3);
            }
        }
    }

    __syncthreads();

    // ---- accumulators -> padded smem scores [128][SSTR] (aliases raw ring) ----
    float* scores = reinterpret_cast<float*>(dyn);
    {
        const int g  = lane >> 2;
        const int t2 = (lane & 3) * 2;
        #pragma unroll
        for (int n = 0; n < 8; n++) {
            const int col = n * 8 + t2;
            scores[(tokb + g) * SSTR + col]         = acc[n][0];
            scores[(tokb + g) * SSTR + col + 1]     = acc[n][1];
            scores[(tokb + g + 8) * SSTR + col]     = acc[n][2];
            scores[(tokb + g + 8) * SSTR + col + 1] = acc[n][3];
        }
    }
    __syncthreads();

    // ---- fast epilogue: 1 thread per token ----
    if (tid < TB) {
        float* srow = scores + tid * SSTR;
        float m = -FLT_MAX;
        #pragma unroll
        for (int e = 0; e < NE; e++) m = fmaxf(m, srow[e]);

        float denom = 0.0f;
        #pragma unroll
        for (int e = 0; e < NE; e++) {
            float q = __expf(srow[e] - m);
            if (q < FLT_MIN) q = 0.0f;
            denom += q;
        }

        bool flag = false;
        float b2 = LN_FLT_MIN + __logf(denom);
        #pragma unroll
        for (int e = 0; e < NE; e++) {
            float d = srow[e] - m;
            if (fabsf(d - LN_FLT_MIN) < EPS_B || fabsf(d - b2) < EPS_B) flag = true;
        }
        {
            unsigned long long used = 0ull;
            float prevv = 0.0f;
            for (int j = 0; j < 9; j++) {
                float best = -FLT_MAX; int bi = 0;
                for (int e = 0; e < NE; e++)
                    if (!((used >> e) & 1ull) && srow[e] > best) { best = srow[e]; bi = e; }
                used |= 1ull << bi;
                if (j > 0 && (prevv - best) < EPS_GAP) flag = true;
                prevv = best;
            }
        }

        float inv = 1.0f / denom;
        #pragma unroll
        for (int e = 0; e < NE; e++) {
            float q = __expf(srow[e] - m);
            if (q < FLT_MIN) q = 0.0f;
            q *= inv;
            if (q < FLT_MIN) q = 0.0f;
            srow[e] = q;
        }

        const int tglob = token0 + tid;
        float* out_w   = out + (size_t)tglob * TOPK;
        float* out_idx = out + (size_t)tokens * TOPK + (size_t)tglob * TOPK;
        #pragma unroll
        for (int j = 0; j < TOPK; j++) {
            float best = -1.0f; int bi = 0;
            for (int e = 0; e < NE; e++)
                if (srow[e] > best) { best = srow[e]; bi = e; }
            srow[bi] = -1.0f;
            out_w[j]   = best;
            out_idx[j] = (float)bi;
        }

        if (flag) {
            int i = atomicAdd(&s_nflag, 1);
            if (i < MAXFLAG) s_flags[i] = tid;
        }
    }
    __syncthreads();

    // ---- in-CTA exact fixup (serial fp32, split-K4 fold) ----
    const int nf = (s_nflag < MAXFLAG) ? s_nflag : MAXFLAG;
    if (nf > 0) {
        const int e  = tid & 63;
        const int sl = tid >> 6;            // slice 0..3
        const int slice = dim >> 2;         // 1024
        float* fixb = reinterpret_cast<float*>(dyn + SM_FIX);

        for (int f0 = 0; f0 < nf; f0 += 2) {
            const int f1 = (f0 + 1 < nf) ? f0 + 1 : f0;
            const float* xr0 = x + (size_t)(token0 + s_flags[f0]) * dim + sl * slice;
            const float* xr1 = x + (size_t)(token0 + s_flags[f1]) * dim + sl * slice;
            const float* wrp = w + (size_t)e * dim + sl * slice;
            float a0 = 0.0f, a1 = 0.0f;
            for (int k = 0; k < slice; k += 4) {
                float4 wv = *reinterpret_cast<const float4*>(wrp + k);
                float4 v0 = *reinterpret_cast<const float4*>(xr0 + k);
                float4 v1 = *reinterpret_cast<const float4*>(xr1 + k);
                a0 = fmaf(v0.x, wv.x, a0); a1 = fmaf(v1.x, wv.x, a1);
                a0 = fmaf(v0.y, wv.y, a0); a1 = fmaf(v1.y, wv.y, a1);
                a0 = fmaf(v0.z, wv.z, a0); a1 = fmaf(v1.z, wv.z, a1);
                a0 = fmaf(v0.w, wv.w, a0); a1 = fmaf(v1.w, wv.w, a1);
            }
            s_part[0][e * 4 + sl] = a0;
            s_part[1][e * 4 + sl] = a1;
            __syncthreads();
            if (tid < NE) {
                float t0 = ((s_part[0][tid * 4] + s_part[0][tid * 4 + 1])
                            + s_part[0][tid * 4 + 2]) + s_part[0][tid * 4 + 3];
                float t1 = ((s_part[1][tid * 4] + s_part[1][tid * 4 + 1])
                            + s_part[1][tid * 4 + 2]) + s_part[1][tid * 4 + 3];
                fixb[f0 * FSTR + tid] = t0;
                fixb[f1 * FSTR + tid] = t1;
            }
            __syncthreads();
        }

        if (tid < nf) {
            float* srow = fixb + tid * FSTR;
            float m = -FLT_MAX;
            for (int ee = 0; ee < NE; ee++) m = fmaxf(m, srow[ee]);
            float denom = 0.0f;
            for (int ee = 0; ee < NE; ee++) {
                float q = expf(srow[ee] - m);
                if (q < FLT_MIN) q = 0.0f;
                srow[ee] = q;
                denom += q;
            }
            float inv = 1.0f / denom;
            for (int ee = 0; ee < NE; ee++) {
                float q = srow[ee] * inv;
                if (q < FLT_MIN) q = 0.0f;
                srow[ee] = q;
            }
            const int tglob = token0 + s_flags[tid];
            float* out_w   = out + (size_t)tglob * TOPK;
            float* out_idx = out + (size_t)tokens * TOPK + (size_t)tglob * TOPK;
            for (int j = 0; j < TOPK; j++) {
                float best = -1.0f; int bi = 0;
                for (int ee = 0; ee < NE; ee++)
                    if (srow[ee] > best) { best = srow[ee]; bi = ee; }
                srow[bi] = -1.0f;
                out_w[j]   = best;
                out_idx[j] = (float)bi;
            }
        }
    }
}

// ================= launch =================
extern "C" void kernel_launch(void* const* d_in, const int* in_sizes, int n_in,
                              void* d_out, int out_size)
{
    const float* x = (const float*)d_in[0];
    const float* w = (const float*)d_in[1];
    // d_in[2] = bias: dead code in the reference

    const int num_experts = in_sizes[2];                 // 64
    const int dim         = in_sizes[1] / num_experts;   // 4096
    const int tokens      = in_sizes[0] / dim;           // 16384
    float* out = (float*)d_out;

    // idempotent, called every time (no static guards allowed)
    cudaFuncSetAttribute(gate_kernel,
                         cudaFuncAttributeMaxDynamicSharedMemorySize, SMEM_DYN);

    prep_w_kernel<<<128, 256>>>(w, dim);
    gate_kernel<<<tokens / TB, NT, SMEM_DYN>>>(x, w, out, dim, tokens);
}